// round 17
// baseline (speedup 1.0000x reference)
#include <cuda_runtime.h>
#include <cuda_bf16.h>
#include <cstdint>

// GaussianKernelDensity: out[m] = coeff + logsumexp_n( -||x_m - X_n||^2 / (2 b^2) )
// M=4096, N=50000, D=64.  (tcgen05 unavailable: harness targets plain sm_100)
//  Launch 1: prep_all — pack x,X to bf16; colc = -|X|^2*s, rowt = +|x|^2*s.
//  Launch 2: kde_main — 18 warps/CTA, 2 CTA/SM. Warps 16-17: cp.async
//            producers (64 rows each) filling a 4-stage SW128 B ring in
//            dynamic smem. Warps 0-15: 2(M)x8(N) consumers, warp tile 32x16
//            — each warp reads ONLY its 16 B-rows (32KB LDSM/tile CTA-wide
//            instead of 64KB) cutting smem-crossbar pressure, the binding
//            resource measured in the prior best config. Pure MUFU ex2
//            epilogue (cheapest per element), cc via prefetched __ldg,
//            row term folded out (applied at final log2).

#define MM 4096
#define NN 50000
#define DD 64
#define NPAD 50176
#define NSPLIT 23
#define CHUNK 2176              // 17 * 128
#define NTILES 17
#define MT 64
#define NT 128
#define STAGE 16384             // 128 rows * 128 B
#define NSTG 4
#define SMEM_DYN (NSTG * STAGE + MT * 128)   // 4 stages + x tile = 73728 B

// device scratch
__device__ __nv_bfloat16 g_Xb[NPAD * DD];
__device__ float         g_CT[NPAD];       // -|X_n|^2 * s  (pad rows: -1000)
__device__ __nv_bfloat16 g_xb[MM * DD];
__device__ float         g_RT[MM];         // +|x_m|^2 * s  (subtracted at end)
__device__ float         g_part[NSPLIT * MM];
__device__ int           g_cnt[MM / MT];

#define LDSM4(r0, r1, r2, r3, addr)                                              \
    asm volatile("ldmatrix.sync.aligned.m8n8.x4.shared.b16 {%0,%1,%2,%3}, [%4];" \
                 : "=r"(r0), "=r"(r1), "=r"(r2), "=r"(r3) : "r"(addr))

__device__ __forceinline__ void cp16(uint32_t dst, const void* src) {
    asm volatile("cp.async.cg.shared.global [%0], [%1], 16;" :: "r"(dst), "l"(src));
}
__device__ __forceinline__ uint32_t smem_u32(const void* p) {
    return (uint32_t)__cvta_generic_to_shared(p);
}
__device__ __forceinline__ void mbar_init(uint32_t a, uint32_t cnt) {
    asm volatile("mbarrier.init.shared.b64 [%0], %1;" :: "r"(a), "r"(cnt) : "memory");
}
__device__ __forceinline__ void mbar_arrive(uint32_t a) {
    asm volatile("mbarrier.arrive.shared.b64 _, [%0];" :: "r"(a) : "memory");
}
__device__ __forceinline__ void cp_async_mbar_arrive(uint32_t a) {
    asm volatile("cp.async.mbarrier.arrive.noinc.shared.b64 [%0];" :: "r"(a) : "memory");
}
__device__ __forceinline__ void mbar_wait(uint32_t a, uint32_t parity) {
    asm volatile(
        "{\n\t.reg .pred P;\n\t"
        "WL_%=:\n\t"
        "mbarrier.try_wait.parity.shared.b64 P, [%0], %1;\n\t"
        "@!P bra WL_%=;\n\t"
        "}" :: "r"(a), "r"(parity) : "memory");
}
__device__ __forceinline__ float ex2(float x) {
    float r;
    asm("ex2.approx.ftz.f32 %0, %1;" : "=f"(r) : "f"(x));
    return r;
}

// ---- packed f32x2 helpers (Blackwell) ----
__device__ __forceinline__ uint64_t pk2(float lo, float hi) {
    uint64_t r;
    asm("mov.b64 %0, {%1, %2};" : "=l"(r) : "f"(lo), "f"(hi));
    return r;
}
__device__ __forceinline__ void upk2(uint32_t& lo, uint32_t& hi, uint64_t v) {
    asm("mov.b64 {%0, %1}, %2;" : "=r"(lo), "=r"(hi) : "l"(v));
}
__device__ __forceinline__ uint64_t fma2(uint64_t a, uint64_t b, uint64_t c) {
    uint64_t d;
    asm("fma.rn.f32x2 %0, %1, %2, %3;" : "=l"(d) : "l"(a), "l"(b), "l"(c));
    return d;
}

// ---------------- prep: pack + fold constants ----------------
__global__ void prep_all(const float* __restrict__ xin,
                         const float* __restrict__ Xin,
                         const float* __restrict__ bw) {
    const float b = bw[0];
    const float inv2 = 1.4426950408889634f / (2.f * b * b);   // log2e / (2 b^2)
    const int blk = blockIdx.x, tid = threadIdx.x;
    const int l8 = tid & 7;

    if (blk < NPAD / 32) {                       // X rows (incl. pad)
        int row = blk * 32 + (tid >> 3);
        uint4 packed = make_uint4(0u, 0u, 0u, 0u);
        __nv_bfloat16* hp = reinterpret_cast<__nv_bfloat16*>(&packed);
        float ss = 0.f;
        if (row < NN) {
            const float4* s4 = reinterpret_cast<const float4*>(Xin + row * DD + l8 * 8);
            float4 a = s4[0], d = s4[1];
            ss = a.x*a.x + a.y*a.y + a.z*a.z + a.w*a.w
               + d.x*d.x + d.y*d.y + d.z*d.z + d.w*d.w;
            hp[0] = __float2bfloat16_rn(a.x); hp[1] = __float2bfloat16_rn(a.y);
            hp[2] = __float2bfloat16_rn(a.z); hp[3] = __float2bfloat16_rn(a.w);
            hp[4] = __float2bfloat16_rn(d.x); hp[5] = __float2bfloat16_rn(d.y);
            hp[6] = __float2bfloat16_rn(d.z); hp[7] = __float2bfloat16_rn(d.w);
        }
        *reinterpret_cast<uint4*>(&g_Xb[row * DD + l8 * 8]) = packed;
        ss += __shfl_xor_sync(0xffffffffu, ss, 1);
        ss += __shfl_xor_sync(0xffffffffu, ss, 2);
        ss += __shfl_xor_sync(0xffffffffu, ss, 4);
        if (l8 == 0) g_CT[row] = (row < NN) ? (-ss * inv2) : -1000.f;
    } else {                                     // x rows
        int row = (blk - NPAD / 32) * 32 + (tid >> 3);
        const float4* s4 = reinterpret_cast<const float4*>(xin + row * DD + l8 * 8);
        float4 a = s4[0], d = s4[1];
        float ss = a.x*a.x + a.y*a.y + a.z*a.z + a.w*a.w
                 + d.x*d.x + d.y*d.y + d.z*d.z + d.w*d.w;
        uint4 packed;
        __nv_bfloat16* hp = reinterpret_cast<__nv_bfloat16*>(&packed);
        hp[0] = __float2bfloat16_rn(a.x); hp[1] = __float2bfloat16_rn(a.y);
        hp[2] = __float2bfloat16_rn(a.z); hp[3] = __float2bfloat16_rn(a.w);
        hp[4] = __float2bfloat16_rn(d.x); hp[5] = __float2bfloat16_rn(d.y);
        hp[6] = __float2bfloat16_rn(d.z); hp[7] = __float2bfloat16_rn(d.w);
        *reinterpret_cast<uint4*>(&g_xb[row * DD + l8 * 8]) = packed;
        ss += __shfl_xor_sync(0xffffffffu, ss, 1);
        ss += __shfl_xor_sync(0xffffffffu, ss, 2);
        ss += __shfl_xor_sync(0xffffffffu, ss, 4);
        if (l8 == 0) g_RT[row] = ss * inv2;      // positive; subtracted at end
    }
}

// ---------------- main: producer/consumer GEMM + MUFU exp2 sum ----------------
__global__ __launch_bounds__(576, 2) void kde_main(const float* __restrict__ bw,
                                                   float* __restrict__ out) {
    extern __shared__ __align__(1024) char dynsmem[];        // 4-stage ring + XS
    char* const S  = dynsmem;                                // 4 * 16KB B ring
    char* const XS = dynsmem + NSTG * STAGE;                 // 8KB x tile
    __shared__ __align__(8) uint64_t mbars[2 * NSTG];        // full[4], empty[4]
    __shared__ float red[8][MT];
    __shared__ int sdone_flag;

    const int tid  = threadIdx.x;
    const int warp = tid >> 5;
    const int lane = tid & 31;

    const int m0    = blockIdx.x * MT;
    const int split = blockIdx.y;
    const int n0    = split * CHUNK;

    const uint32_t Sb = smem_u32(S);
    uint32_t fullA[NSTG], emptyA[NSTG];
    #pragma unroll
    for (int s = 0; s < NSTG; s++) {
        fullA[s]  = smem_u32(&mbars[s]);
        emptyA[s] = smem_u32(&mbars[NSTG + s]);
    }

    if (tid == 0) {
        #pragma unroll
        for (int s = 0; s < NSTG; s++) {
            mbar_init(fullA[s], 64);     // 2 producer warps x 32 lanes (noinc)
            mbar_init(emptyA[s], 16);    // 16 consumer warps (lane 0)
        }
    }

    // first 256 threads stage the x tile, swizzled
    if (tid < 256) {
        int row = tid >> 2, q = tid & 3;
        const uint4* s = reinterpret_cast<const uint4*>(g_xb + (m0 + row) * DD + q * 16);
        uint4 v0 = s[0], v1 = s[1];
        int base = row * 128;
        int msk = row & 7;
        *reinterpret_cast<uint4*>(XS + base + (((2 * q)     ^ msk) * 16)) = v0;
        *reinterpret_cast<uint4*>(XS + base + (((2 * q + 1) ^ msk) * 16)) = v1;
    }
    __syncthreads();   // mbarriers initialized + x tile visible

    if (warp >= 16) {
        // ================= producer warps 16,17 (64 rows each) ============
        const int pr = warp - 16;            // 0: rows 0-63, 1: rows 64-127
        const int r0 = lane >> 3, ch = lane & 7;
        const int qbase = pr * 16;           // q in [qbase, qbase+16)
        const __nv_bfloat16* src = g_Xb + (n0 + qbase * 4 + r0) * DD + ch * 8;
        const uint32_t de  = (uint32_t)(r0 * 128 + ((ch ^ r0) * 16));
        const uint32_t dof = (uint32_t)(r0 * 128 + 512 + ((ch ^ r0 ^ 4) * 16));
        for (int it = 0; it < NTILES; it++) {
            const int st = it & 3;
            if (it >= NSTG) mbar_wait(emptyA[st], ((it >> 2) - 1) & 1);
            const uint32_t base = Sb + (uint32_t)st * STAGE;
            #pragma unroll
            for (int q = 0; q < 16; q += 2) {
                cp16(base + (qbase + q) * 512 + de,  src);  src += 4 * DD;
                cp16(base + (qbase + q) * 512 + dof, src);  src += 4 * DD;
            }
            src += 64 * DD;   // skip the other producer's 64 rows
            cp_async_mbar_arrive(fullA[st]);
        }
    } else {
        // ======== consumer warps 0-15: 2(M) x 8(N), warp tile 32x16 =======
        const int g = lane >> 2;
        const int c = lane & 3;
        const int wm = warp >> 3;     // 0..1 (M: 32-row group)
        const int wn = warp & 7;      // 0..7 (N: 16-col group)

        const float b    = bw[0];
        const float inv4 = 1.4426950408889634f / (b * b);   // log2e / b^2
        const uint64_t inv42 = pk2(inv4, inv4);

        // A fragments for the whole lifetime (32 rows x K=64 -> 32 regs)
        const int lr = (lane & 7) + ((lane >> 3) & 1) * 8;
        const int cb = lane >> 4;
        uint32_t afr[4][8];
        #pragma unroll
        for (int i = 0; i < 2; i++) {
            int rowp = wm * 32 + i * 16 + lr;
            uint32_t rb = smem_u32(XS) + rowp * 128;
            int rm = rowp & 7;
            #pragma unroll
            for (int ks = 0; ks < 4; ks++) {
                uint32_t a0, a1, a2, a3;
                LDSM4(a0, a1, a2, a3, rb + (((ks * 2 + cb) ^ rm) * 16));
                afr[ks][i * 4 + 0] = a0; afr[ks][i * 4 + 1] = a1;
                afr[ks][i * 4 + 2] = a2; afr[ks][i * 4 + 3] = a3;
            }
        }

        // this warp's ONLY 16 B-rows (N block): rows wn*16 + lr
        uint32_t rB_off; int rB_msk;
        {
            int rowp = wn * 16 + lr;
            rB_off = (uint32_t)(rowp * 128);
            rB_msk = rowp & 7;
        }

        const float* gc = g_CT + n0 + wn * 16 + 2 * c;   // + jn*8 + it*NT
        float2 cv[2];
        #pragma unroll
        for (int j = 0; j < 2; j++) cv[j] = __ldg((const float2*)(gc + j * 8));

        float acc[2][2][4];                 // [i (M-half)][jn (n8)][q]
        float sums[4] = {0.f, 0.f, 0.f, 0.f};

        for (int it = 0; it < NTILES; it++) {
            const int st = it & 3;
            const uint32_t stb = Sb + (uint32_t)st * STAGE;
            mbar_wait(fullA[st], (it >> 2) & 1);

            uint64_t cc0 = pk2(cv[0].x, cv[0].y);
            uint64_t cc1 = pk2(cv[1].x, cv[1].y);
            const int pf = (it + 1 < NTILES) ? it + 1 : it;
            #pragma unroll
            for (int j = 0; j < 2; j++)
                cv[j] = __ldg((const float2*)(gc + pf * NT + j * 8));

            // ---- burst: 4 LDSM + 16 MMAs over this warp's 16 N-rows ----
            #pragma unroll
            for (int i = 0; i < 2; i++)
                #pragma unroll
                for (int jn = 0; jn < 2; jn++)
                    #pragma unroll
                    for (int q = 0; q < 4; q++) acc[i][jn][q] = 0.f;
            #pragma unroll
            for (int ks = 0; ks < 4; ks++) {
                uint32_t b0, b1, b2, b3;
                uint32_t addr = stb + rB_off + (((ks * 2 + cb) ^ rB_msk) * 16);
                LDSM4(b0, b1, b2, b3, addr);
                #pragma unroll
                for (int i = 0; i < 2; i++) {
                    asm volatile(
                        "mma.sync.aligned.m16n8k16.row.col.f32.bf16.bf16.f32 "
                        "{%0,%1,%2,%3}, {%4,%5,%6,%7}, {%8,%9}, {%0,%1,%2,%3};"
                        : "+f"(acc[i][0][0]), "+f"(acc[i][0][1]),
                          "+f"(acc[i][0][2]), "+f"(acc[i][0][3])
                        : "r"(afr[ks][i * 4 + 0]), "r"(afr[ks][i * 4 + 1]),
                          "r"(afr[ks][i * 4 + 2]), "r"(afr[ks][i * 4 + 3]),
                          "r"(b0), "r"(b2));
                    asm volatile(
                        "mma.sync.aligned.m16n8k16.row.col.f32.bf16.bf16.f32 "
                        "{%0,%1,%2,%3}, {%4,%5,%6,%7}, {%8,%9}, {%0,%1,%2,%3};"
                        : "+f"(acc[i][1][0]), "+f"(acc[i][1][1]),
                          "+f"(acc[i][1][2]), "+f"(acc[i][1][3])
                        : "r"(afr[ks][i * 4 + 0]), "r"(afr[ks][i * 4 + 1]),
                          "r"(afr[ks][i * 4 + 2]), "r"(afr[ks][i * 4 + 3]),
                          "r"(b1), "r"(b3));
                }
            }
            if (lane == 0) mbar_arrive(emptyA[st]);   // all LDSMs done

            // ---- epilogue: e = ex2(acc*s + cc), 4 independent row chains ----
            #pragma unroll
            for (int r = 0; r < 4; r++) {
                const int i = r >> 1, hf = r & 1;
                uint64_t v0 = fma2(pk2(acc[i][0][hf * 2], acc[i][0][hf * 2 + 1]),
                                   inv42, cc0);
                uint64_t v1 = fma2(pk2(acc[i][1][hf * 2], acc[i][1][hf * 2 + 1]),
                                   inv42, cc1);
                uint32_t a, d;
                upk2(a, d, v0);
                sums[r] += ex2(__uint_as_float(a));
                sums[r] += ex2(__uint_as_float(d));
                upk2(a, d, v1);
                sums[r] += ex2(__uint_as_float(a));
                sums[r] += ex2(__uint_as_float(d));
            }
        }

        // quad reduce, store to red[] (warp owns red[wn][wm*32 .. +31])
        #pragma unroll
        for (int r = 0; r < 4; r++) {
            float sv = sums[r];
            sv += __shfl_xor_sync(0xffffffffu, sv, 1);
            sv += __shfl_xor_sync(0xffffffffu, sv, 2);
            if (c == 0) {
                int rl = wm * 32 + (r >> 1) * 16 + (r & 1) * 8 + g;
                red[wn][rl] = sv;
            }
        }
    }

    __syncthreads();
    if (tid < MT) {
        float tot = 0.f;
        #pragma unroll
        for (int w = 0; w < 8; w++) tot += red[w][tid];
        g_part[split * MM + m0 + tid] = tot;
    }
    __syncthreads();

    // ---- tail CTA per m-block merges the 23 split sums ----
    if (tid == 0) {
        __threadfence();
        int old = atomicAdd(&g_cnt[blockIdx.x], 1);
        sdone_flag = (old == NSPLIT - 1) ? 1 : 0;
        if (sdone_flag) __threadfence();
    }
    __syncthreads();
    if (sdone_flag) {
        if (tid < MT) {
            float tot = 0.f;
            #pragma unroll
            for (int s = 0; s < NSPLIT; s++) tot += __ldcg(&g_part[s * MM + m0 + tid]);
            // coeff = -ln(50000) - 32*ln(2*pi); row term applied here
            out[m0 + tid] = -69.63184443f
                          + (log2f(tot) - g_RT[m0 + tid]) * 0.6931471805599453f;
        }
        __syncthreads();
        if (tid == 0) g_cnt[blockIdx.x] = 0;   // reset for next graph replay
    }
}

extern "C" void kernel_launch(void* const* d_in, const int* in_sizes, int n_in,
                              void* d_out, int out_size) {
    const float* x  = (const float*)d_in[0];   // [4096, 64]
    const float* X  = (const float*)d_in[1];   // [50000, 64]
    const float* bw = (const float*)d_in[2];   // [1]

    // opt-in to >48KB dynamic smem (idempotent; not an allocation)
    cudaFuncSetAttribute(kde_main, cudaFuncAttributeMaxDynamicSharedMemorySize,
                         SMEM_DYN);

    prep_all<<<NPAD / 32 + MM / 32, 256>>>(x, X, bw);   // 1696 blocks

    dim3 grid(MM / MT, NSPLIT);                         // (64, 23)
    kde_main<<<grid, 576, SMEM_DYN>>>(bw, (float*)d_out);
}